// round 6
// baseline (speedup 1.0000x reference)
#include <cuda_runtime.h>
#include <math.h>

#define NB 4096
#define NS 64
#define NY 256
#define NH 128
#define NE 32
#define NKG 8
#define NKA 20
#define NNC 50
#define NNT 5

typedef unsigned long long ull;

__device__ __forceinline__ float sigmoidf_(float v) { return 1.f / (1.f + expf(-v)); }

#define FMA2(acc, a, b) asm("fma.rn.f32x2 %0, %1, %2, %0;" : "+l"(acc) : "l"(a), "l"(b))
#define PACK2(out, lo, hi) asm("mov.b64 %0, {%1, %2};" : "=l"(out) : "f"(lo), "f"(hi))
#define UNPACK2(lo, hi, in) asm("mov.b64 {%0, %1}, %2;" : "=f"(lo), "=f"(hi) : "l"(in))

// One block = 8 batch rows, 256 threads, 4 blocks/SM -> 512 blocks = single wave.
__global__ __launch_bounds__(256, 4) void wine_fused(
    const float4* __restrict__ x4,
    const int*   __restrict__ grapes,
    const float* __restrict__ grapes_scales,
    const int*   __restrict__ aromas,
    const float* __restrict__ aromas_scales,
    const float* __restrict__ W_common, const float* __restrict__ b_common,
    const float* __restrict__ W_country, const float* __restrict__ b_country,
    const float* __restrict__ W_type,   const float* __restrict__ b_type,
    const float* __restrict__ W_taste,  const float* __restrict__ b_taste,
    const float* __restrict__ W_aroma,  const float* __restrict__ b_aroma,
    const float* __restrict__ W_grape,  const float* __restrict__ b_grape,
    const float* __restrict__ grapes_emb,
    const float* __restrict__ aroma_emb,
    float* __restrict__ out)
{
    __shared__ __align__(16) float x_sm[8 * NY];       // 8 KB
    __shared__ float red[4][128][9];                   // 18.4 KB, padded banks
    __shared__ __align__(16) float y_sm[8 * NH];       // 4 KB
    __shared__ __align__(16) float yg_sm[8 * NE];      // 1 KB
    __shared__ __align__(16) float ya_sm[8 * NE];      // 1 KB

    const int tid = threadIdx.x;
    const int b0  = blockIdx.x * 8;

    // ---------- Hoisted phase-4 index/scale loads (hide under the stream) ----------
    int   g_idx = 0;   float g_sc = 0.f;
    int   a_idx = 0;   float a_sc = 0.f;
    if (tid < 64) {
        const int r = tid >> 3, k = tid & 7;
        g_idx = grapes[(b0 + r) * NKG + k];
        g_sc  = grapes_scales[(b0 + r) * NKG + k];
    } else if (tid < 224) {
        const int task = tid - 64;
        const int r = task / NKA, k = task % NKA;
        a_idx = aromas[(b0 + r) * NKA + k];
        a_sc  = aromas_scales[(b0 + r) * NKA + k];
    }

    // ---------- Phase 1: max-pool. 512 (row, col4) tasks, 2 interleaved per thread ----------
    {
        const int r0 = tid >> 6,          c40 = tid & 63;
        const int r1 = (tid + 256) >> 6,  c41 = tid & 63;
        const float4* p0 = x4 + (size_t)(b0 + r0) * (NS * NY / 4) + c40;
        const float4* p1 = x4 + (size_t)(b0 + r1) * (NS * NY / 4) + c41;
        float4 a0 = p0[0 * 64], a1 = p0[1 * 64], a2 = p0[2 * 64], a3 = p0[3 * 64];
        float4 b0v = p1[0 * 64], b1v = p1[1 * 64], b2v = p1[2 * 64], b3v = p1[3 * 64];
        #pragma unroll
        for (int s = 4; s < NS; s += 4) {
            float4 u0 = p0[(s + 0) * 64], u1 = p0[(s + 1) * 64];
            float4 u2 = p0[(s + 2) * 64], u3 = p0[(s + 3) * 64];
            float4 w0 = p1[(s + 0) * 64], w1 = p1[(s + 1) * 64];
            float4 w2 = p1[(s + 2) * 64], w3 = p1[(s + 3) * 64];
            a0.x = fmaxf(a0.x, u0.x); a0.y = fmaxf(a0.y, u0.y); a0.z = fmaxf(a0.z, u0.z); a0.w = fmaxf(a0.w, u0.w);
            a1.x = fmaxf(a1.x, u1.x); a1.y = fmaxf(a1.y, u1.y); a1.z = fmaxf(a1.z, u1.z); a1.w = fmaxf(a1.w, u1.w);
            a2.x = fmaxf(a2.x, u2.x); a2.y = fmaxf(a2.y, u2.y); a2.z = fmaxf(a2.z, u2.z); a2.w = fmaxf(a2.w, u2.w);
            a3.x = fmaxf(a3.x, u3.x); a3.y = fmaxf(a3.y, u3.y); a3.z = fmaxf(a3.z, u3.z); a3.w = fmaxf(a3.w, u3.w);
            b0v.x = fmaxf(b0v.x, w0.x); b0v.y = fmaxf(b0v.y, w0.y); b0v.z = fmaxf(b0v.z, w0.z); b0v.w = fmaxf(b0v.w, w0.w);
            b1v.x = fmaxf(b1v.x, w1.x); b1v.y = fmaxf(b1v.y, w1.y); b1v.z = fmaxf(b1v.z, w1.z); b1v.w = fmaxf(b1v.w, w1.w);
            b2v.x = fmaxf(b2v.x, w2.x); b2v.y = fmaxf(b2v.y, w2.y); b2v.z = fmaxf(b2v.z, w2.z); b2v.w = fmaxf(b2v.w, w2.w);
            b3v.x = fmaxf(b3v.x, w3.x); b3v.y = fmaxf(b3v.y, w3.y); b3v.z = fmaxf(b3v.z, w3.z); b3v.w = fmaxf(b3v.w, w3.w);
        }
        float4 ra, rb;
        ra.x = fmaxf(fmaxf(a0.x, a1.x), fmaxf(a2.x, a3.x));
        ra.y = fmaxf(fmaxf(a0.y, a1.y), fmaxf(a2.y, a3.y));
        ra.z = fmaxf(fmaxf(a0.z, a1.z), fmaxf(a2.z, a3.z));
        ra.w = fmaxf(fmaxf(a0.w, a1.w), fmaxf(a2.w, a3.w));
        rb.x = fmaxf(fmaxf(b0v.x, b1v.x), fmaxf(b2v.x, b3v.x));
        rb.y = fmaxf(fmaxf(b0v.y, b1v.y), fmaxf(b2v.y, b3v.y));
        rb.z = fmaxf(fmaxf(b0v.z, b1v.z), fmaxf(b2v.z, b3v.z));
        rb.w = fmaxf(fmaxf(b0v.w, b1v.w), fmaxf(b2v.w, b3v.w));
        reinterpret_cast<float4*>(x_sm)[r0 * (NY / 4) + c40] = ra;
        reinterpret_cast<float4*>(x_sm)[r1 * (NY / 4) + c41] = rb;
    }
    __syncthreads();

    // ---------- Phase 2: GEMM1, 2 cols/thread, 4-way split-K, f32x2 ----------
    {
        const int cp = tid & 63;          // col pair: cols 2cp, 2cp+1
        const int kq = tid >> 6;          // 0..3, K range [kq*64, kq*64+64)
        const float2* W2 = reinterpret_cast<const float2*>(W_common);
        ull acc0[8], acc1[8];
        #pragma unroll
        for (int j = 0; j < 8; j++) { acc0[j] = 0ull; acc1[j] = 0ull; }
        const int kb = kq * 64;
        #pragma unroll 4
        for (int i = kb; i < kb + 64; i += 4) {
            float2 w0 = W2[(i + 0) * 64 + cp];
            float2 w1 = W2[(i + 1) * 64 + cp];
            float2 w2 = W2[(i + 2) * 64 + cp];
            float2 w3 = W2[(i + 3) * 64 + cp];
            ull wa0, wb0, wa1, wb1;
            PACK2(wa0, w0.x, w1.x); PACK2(wb0, w2.x, w3.x);
            PACK2(wa1, w0.y, w1.y); PACK2(wb1, w2.y, w3.y);
            #pragma unroll
            for (int j = 0; j < 8; j++) {
                ulonglong2 xv = *reinterpret_cast<const ulonglong2*>(&x_sm[j * NY + i]);
                FMA2(acc0[j], xv.x, wa0);
                FMA2(acc0[j], xv.y, wb0);
                FMA2(acc1[j], xv.x, wa1);
                FMA2(acc1[j], xv.y, wb1);
            }
        }
        #pragma unroll
        for (int j = 0; j < 8; j++) {
            float lo, hi;
            UNPACK2(lo, hi, acc0[j]);
            red[kq][2 * cp + 0][j] = lo + hi;
            UNPACK2(lo, hi, acc1[j]);
            red[kq][2 * cp + 1][j] = lo + hi;
        }
    }
    __syncthreads();
    if (tid < NH) {
        const int h = tid;
        float bb = b_common[h];
        #pragma unroll
        for (int j = 0; j < 8; j++) {
            float v = red[0][h][j] + red[1][h][j] + red[2][h][j] + red[3][h][j] + bb;
            y_sm[j * NH + h] = (v > 0.f) ? v : expm1f(v);
        }
    }
    __syncthreads();

    // ---------- Phase 3: all heads as one 128x120 GEMM, split-K x2, f32x2 ----------
    {
        const int c  = tid & 127;
        const int kq = tid >> 7;
        const int kb = kq * 64;
        ull acc2[8];
        #pragma unroll
        for (int j = 0; j < 8; j++) acc2[j] = 0ull;

        const float* Wp; int stride; int cc = c;
        if (c < NNC)       { Wp = W_country; stride = NNC; }
        else if (c == NNC) { Wp = W_type;    stride = 1;  cc = 0; }
        else if (c < 56)   { Wp = W_taste;   stride = NNT; cc = c - 51; }
        else if (c < 88)   { Wp = W_grape;   stride = NE;  cc = c - 56; }
        else if (c < 120)  { Wp = W_aroma;   stride = NE;  cc = c - 88; }
        else               { Wp = W_country; stride = NNC; cc = 0; }   // dummy lanes

        #pragma unroll 4
        for (int i = kb; i < kb + 64; i += 4) {
            float wa0 = Wp[(i + 0) * stride + cc];
            float wa1 = Wp[(i + 1) * stride + cc];
            float wb0 = Wp[(i + 2) * stride + cc];
            float wb1 = Wp[(i + 3) * stride + cc];
            ull wpa, wpb;
            PACK2(wpa, wa0, wa1);
            PACK2(wpb, wb0, wb1);
            #pragma unroll
            for (int j = 0; j < 8; j++) {
                ulonglong2 yv = *reinterpret_cast<const ulonglong2*>(&y_sm[j * NH + i]);
                FMA2(acc2[j], yv.x, wpa);
                FMA2(acc2[j], yv.y, wpb);
            }
        }
        if (c < 120) {
            #pragma unroll
            for (int j = 0; j < 8; j++) {
                float lo, hi;
                UNPACK2(lo, hi, acc2[j]);
                red[kq][c][j] = lo + hi;
            }
        }
    }
    __syncthreads();
    if (tid < 120) {
        const int c = tid;
        float s[8];
        #pragma unroll
        for (int j = 0; j < 8; j++)
            s[j] = red[0][c][j] + red[1][c][j];
        if (c < NNC) {
            float bb = b_country[c];
            #pragma unroll
            for (int j = 0; j < 8; j++)
                out[(size_t)(b0 + j) * NNC + c] = s[j] + bb;
        } else if (c == NNC) {
            float bb = b_type[0];
            #pragma unroll
            for (int j = 0; j < 8; j++)
                out[(size_t)NB * NNC + (b0 + j)] = sigmoidf_(s[j] + bb);
        } else if (c < 56) {
            const int cc = c - 51;
            float bb = b_taste[cc];
            #pragma unroll
            for (int j = 0; j < 8; j++)
                out[(size_t)NB * 51 + (size_t)(b0 + j) * NNT + cc] = sigmoidf_(s[j] + bb);
        } else if (c < 88) {
            const int e = c - 56;
            float bb = b_grape[e];
            #pragma unroll
            for (int j = 0; j < 8; j++) yg_sm[j * NE + e] = s[j] + bb;
        } else {
            const int e = c - 88;
            float bb = b_aroma[e];
            #pragma unroll
            for (int j = 0; j < 8; j++) ya_sm[j * NE + e] = s[j] + bb;
        }
    }
    __syncthreads();

    // ---------- Phase 4: ragged embedding scoring (indices preloaded) ----------
    if (tid < 64) {                               // 8 rows x 8 grape slots
        const int r = tid >> 3, k = tid & 7;
        const int b = b0 + r;
        const float4* emb = reinterpret_cast<const float4*>(grapes_emb) + (size_t)g_idx * (NE / 4);
        const float4* yv4 = reinterpret_cast<const float4*>(&yg_sm[r * NE]);
        float acc = 0.f;
        #pragma unroll
        for (int i = 0; i < NE / 4; i++) {
            float4 ev = emb[i], yv = yv4[i];
            acc += ev.x * yv.x + ev.y * yv.y + ev.z * yv.z + ev.w * yv.w;
        }
        float mask = (g_idx != 0) ? 1.f : 0.f;
        out[(size_t)NB * 56 + (size_t)b * NKG + k] = sigmoidf_(acc) * mask;
        out[(size_t)NB * 64 + (size_t)b * NKG + k] = g_sc;
    } else if (tid < 224) {                       // 8 rows x 20 aroma slots
        const int task = tid - 64;
        const int r = task / NKA, k = task % NKA;
        const int b = b0 + r;
        const float4* emb = reinterpret_cast<const float4*>(aroma_emb) + (size_t)a_idx * (NE / 4);
        const float4* yv4 = reinterpret_cast<const float4*>(&ya_sm[r * NE]);
        float acc = 0.f;
        #pragma unroll
        for (int i = 0; i < NE / 4; i++) {
            float4 ev = emb[i], yv = yv4[i];
            acc += ev.x * yv.x + ev.y * yv.y + ev.z * yv.z + ev.w * yv.w;
        }
        float mask = (a_sc != 0.f) ? 1.f : 0.f;
        out[(size_t)NB * 72 + (size_t)b * NKA + k] = sigmoidf_(acc) * mask;
        out[(size_t)NB * 92 + (size_t)b * NKA + k] = a_sc;
    }
}

extern "C" void kernel_launch(void* const* d_in, const int* in_sizes, int n_in,
                              void* d_out, int out_size) {
    const float* x_enc          = (const float*)d_in[0];
    const int*   grapes         = (const int*)  d_in[1];
    const float* grapes_scales  = (const float*)d_in[2];
    const int*   aromas         = (const int*)  d_in[3];
    const float* aromas_scales  = (const float*)d_in[4];
    const float* W_common       = (const float*)d_in[5];
    const float* b_common       = (const float*)d_in[6];
    const float* W_country      = (const float*)d_in[7];
    const float* b_country      = (const float*)d_in[8];
    const float* W_type         = (const float*)d_in[9];
    const float* b_type         = (const float*)d_in[10];
    const float* W_taste        = (const float*)d_in[11];
    const float* b_taste        = (const float*)d_in[12];
    const float* W_aroma        = (const float*)d_in[13];
    const float* b_aroma        = (const float*)d_in[14];
    const float* W_grape        = (const float*)d_in[15];
    const float* b_grape        = (const float*)d_in[16];
    const float* grapes_emb     = (const float*)d_in[17];
    const float* aroma_emb      = (const float*)d_in[18];
    float* out = (float*)d_out;

    wine_fused<<<NB / 8, 256>>>(reinterpret_cast<const float4*>(x_enc),
                                grapes, grapes_scales, aromas, aromas_scales,
                                W_common, b_common, W_country, b_country,
                                W_type, b_type, W_taste, b_taste,
                                W_aroma, b_aroma, W_grape, b_grape,
                                grapes_emb, aroma_emb, out);
}

// round 7
// speedup vs baseline: 1.1317x; 1.1317x over previous
#include <cuda_runtime.h>
#include <math.h>

#define NB 4096
#define NS 64
#define NY 256
#define NH 128
#define NE 32
#define NKG 8
#define NKA 20
#define NNC 50
#define NNT 5

typedef unsigned long long ull;

__device__ __forceinline__ float sigmoidf_(float v) { return 1.f / (1.f + expf(-v)); }

#define FMA2(acc, a, b) asm("fma.rn.f32x2 %0, %1, %2, %0;" : "+l"(acc) : "l"(a), "l"(b))
#define PACK2(out, lo, hi) asm("mov.b64 %0, {%1, %2};" : "=l"(out) : "f"(lo), "f"(hi))
#define UNPACK2(lo, hi, in) asm("mov.b64 {%0, %1}, %2;" : "=f"(lo), "=f"(hi) : "l"(in))

#define FMAX4(m, v) do { \
    m.x = fmaxf(m.x, v.x); m.y = fmaxf(m.y, v.y); \
    m.z = fmaxf(m.z, v.z); m.w = fmaxf(m.w, v.w); } while (0)

// heads weight-select (same mapping for every heads GEMM)
__device__ __forceinline__ void head_sel(int c,
    const float* W_country, const float* W_type, const float* W_taste,
    const float* W_grape, const float* W_aroma,
    const float** Wp, int* stride, int* cc)
{
    if (c < NNC)       { *Wp = W_country; *stride = NNC; *cc = c; }
    else if (c == NNC) { *Wp = W_type;    *stride = 1;   *cc = 0; }
    else if (c < 56)   { *Wp = W_taste;   *stride = NNT; *cc = c - 51; }
    else if (c < 88)   { *Wp = W_grape;   *stride = NE;  *cc = c - 56; }
    else if (c < 120)  { *Wp = W_aroma;   *stride = NE;  *cc = c - 88; }
    else               { *Wp = W_country; *stride = NNC; *cc = 0; }   // dummy lanes
}

// one K-step (4 elems) of a column GEMM, f32x2
#define GEMM_STEP(Wsrc, STRIDE, CC, XBUF, ROWSTRIDE, I, ACC) do {              \
    float _w0 = (Wsrc)[((I) + 0) * (STRIDE) + (CC)];                            \
    float _w1 = (Wsrc)[((I) + 1) * (STRIDE) + (CC)];                            \
    float _w2 = (Wsrc)[((I) + 2) * (STRIDE) + (CC)];                            \
    float _w3 = (Wsrc)[((I) + 3) * (STRIDE) + (CC)];                            \
    ull _wpa, _wpb;                                                             \
    PACK2(_wpa, _w0, _w1); PACK2(_wpb, _w2, _w3);                               \
    _Pragma("unroll")                                                           \
    for (int _j = 0; _j < 8; _j++) {                                            \
        ulonglong2 _xv = *reinterpret_cast<const ulonglong2*>(                  \
            &(XBUF)[_j * (ROWSTRIDE) + (I)]);                                   \
        FMA2((ACC)[_j], _xv.x, _wpa);                                           \
        FMA2((ACC)[_j], _xv.y, _wpb);                                           \
    } } while (0)

// ragged scoring for one 8-row group starting at global row gb
__device__ __forceinline__ void ragged_group(
    int tid, int gb,
    const int* __restrict__ grapes, const float* __restrict__ grapes_scales,
    const int* __restrict__ aromas, const float* __restrict__ aromas_scales,
    const float* __restrict__ grapes_emb, const float* __restrict__ aroma_emb,
    const float* yg, const float* ya, float* __restrict__ out)
{
    if (tid < 64) {
        const int r = tid >> 3, k = tid & 7;
        const int b = gb + r;
        const int   idx = grapes[b * NKG + k];
        const float sc  = grapes_scales[b * NKG + k];
        const float4* emb = reinterpret_cast<const float4*>(grapes_emb) + (size_t)idx * (NE / 4);
        const float4* yv4 = reinterpret_cast<const float4*>(&yg[r * NE]);
        float acc = 0.f;
        #pragma unroll
        for (int i = 0; i < NE / 4; i++) {
            float4 ev = emb[i], yv = yv4[i];
            acc += ev.x * yv.x + ev.y * yv.y + ev.z * yv.z + ev.w * yv.w;
        }
        float mask = (idx != 0) ? 1.f : 0.f;
        out[(size_t)NB * 56 + (size_t)b * NKG + k] = sigmoidf_(acc) * mask;
        out[(size_t)NB * 64 + (size_t)b * NKG + k] = sc;
    } else if (tid < 224) {
        const int task = tid - 64;
        const int r = task / NKA, k = task % NKA;
        const int b = gb + r;
        const int   idx = aromas[b * NKA + k];
        const float sc  = aromas_scales[b * NKA + k];
        const float4* emb = reinterpret_cast<const float4*>(aroma_emb) + (size_t)idx * (NE / 4);
        const float4* yv4 = reinterpret_cast<const float4*>(&ya[r * NE]);
        float acc = 0.f;
        #pragma unroll
        for (int i = 0; i < NE / 4; i++) {
            float4 ev = emb[i], yv = yv4[i];
            acc += ev.x * yv.x + ev.y * yv.y + ev.z * yv.z + ev.w * yv.w;
        }
        float mask = (sc != 0.f) ? 1.f : 0.f;
        out[(size_t)NB * 72 + (size_t)b * NKA + k] = sigmoidf_(acc) * mask;
        out[(size_t)NB * 92 + (size_t)b * NKA + k] = sc;
    }
}

// One block = 16 batch rows (two pipelined groups of 8), 256 threads, grid 256.
__global__ __launch_bounds__(256, 2) void wine_fused(
    const float4* __restrict__ x4,
    const int*   __restrict__ grapes,
    const float* __restrict__ grapes_scales,
    const int*   __restrict__ aromas,
    const float* __restrict__ aromas_scales,
    const float* __restrict__ W_common, const float* __restrict__ b_common,
    const float* __restrict__ W_country, const float* __restrict__ b_country,
    const float* __restrict__ W_type,   const float* __restrict__ b_type,
    const float* __restrict__ W_taste,  const float* __restrict__ b_taste,
    const float* __restrict__ W_aroma,  const float* __restrict__ b_aroma,
    const float* __restrict__ W_grape,  const float* __restrict__ b_grape,
    const float* __restrict__ grapes_emb,
    const float* __restrict__ aroma_emb,
    float* __restrict__ out)
{
    __shared__ __align__(16) float x_smA[8 * NY];     // 8 KB
    __shared__ __align__(16) float x_smB[8 * NY];     // 8 KB
    __shared__ float red[2][128][9];                  // 9.2 KB  (GEMM1 A, then GEMM1 B)
    __shared__ float redH[2][128][9];                 // 9.2 KB  (heads A, then heads B)
    __shared__ __align__(16) float y_smA[8 * NH];     // 4 KB
    __shared__ __align__(16) float y_smB[8 * NH];     // 4 KB
    __shared__ __align__(16) float yg_sm[16 * NE];    // 2 KB (rows 0-7 = A, 8-15 = B)
    __shared__ __align__(16) float ya_sm[16 * NE];    // 2 KB

    const int tid = threadIdx.x;
    const int b0  = blockIdx.x * 16;
    const float NEGINF = __int_as_float(0xff800000);

    const int r0 = tid >> 6, c4 = tid & 63;
    const int r1 = (tid + 256) >> 6;

    // ================= P1: stream group A (rows b0..b0+7) =================
    #pragma unroll
    for (int q = 0; q < 2; q++) {
        const int task = tid + q * 256;
        const int r  = task >> 6;
        const float4* p = x4 + (size_t)(b0 + r) * (NS * NY / 4) + c4;
        float4 m0 = p[0 * 64], m1 = p[1 * 64], m2 = p[2 * 64], m3 = p[3 * 64];
        #pragma unroll
        for (int s = 4; s < NS; s += 4) {
            float4 v0 = p[(s + 0) * 64], v1 = p[(s + 1) * 64];
            float4 v2 = p[(s + 2) * 64], v3 = p[(s + 3) * 64];
            FMAX4(m0, v0); FMAX4(m1, v1); FMAX4(m2, v2); FMAX4(m3, v3);
        }
        float4 rr;
        rr.x = fmaxf(fmaxf(m0.x, m1.x), fmaxf(m2.x, m3.x));
        rr.y = fmaxf(fmaxf(m0.y, m1.y), fmaxf(m2.y, m3.y));
        rr.z = fmaxf(fmaxf(m0.z, m1.z), fmaxf(m2.z, m3.z));
        rr.w = fmaxf(fmaxf(m0.w, m1.w), fmaxf(m2.w, m3.w));
        reinterpret_cast<float4*>(x_smA)[r * (NY / 4) + c4] = rr;
    }
    __syncthreads();

    // ========== P2: GEMM1(A) fused with stream of group B (rows b0+8..b0+15) ==========
    {
        const int h  = tid & 127;
        const int kq = tid >> 7;
        const int kb = kq * 128;

        const float4* p0 = x4 + (size_t)(b0 + 8 + r0) * (NS * NY / 4) + c4;
        const float4* p1 = x4 + (size_t)(b0 + 8 + r1) * (NS * NY / 4) + c4;
        float4 m0 = make_float4(NEGINF, NEGINF, NEGINF, NEGINF);
        float4 m1 = m0;

        ull acc[8];
        #pragma unroll
        for (int j = 0; j < 8; j++) acc[j] = 0ull;

        #pragma unroll 2
        for (int it = 0; it < 32; it++) {
            // stream B: 4 independent LDG.128 per iteration
            float4 u0 = p0[(2 * it + 0) * 64];
            float4 u1 = p0[(2 * it + 1) * 64];
            float4 v0 = p1[(2 * it + 0) * 64];
            float4 v1 = p1[(2 * it + 1) * 64];
            // GEMM1(A) step
            GEMM_STEP(W_common, NH, h, x_smA, NY, kb + it * 4, acc);
            FMAX4(m0, u0); FMAX4(m0, u1);
            FMAX4(m1, v0); FMAX4(m1, v1);
        }
        #pragma unroll
        for (int j = 0; j < 8; j++) {
            float lo, hi;
            UNPACK2(lo, hi, acc[j]);
            red[kq][h][j] = lo + hi;
        }
        reinterpret_cast<float4*>(x_smB)[r0 * (NY / 4) + c4] = m0;
        reinterpret_cast<float4*>(x_smB)[r1 * (NY / 4) + c4] = m1;
    }
    __syncthreads();

    // P2b: reduce -> y_A (elu)
    if (tid < NH) {
        float bb = b_common[tid];
        #pragma unroll
        for (int j = 0; j < 8; j++) {
            float v = red[0][tid][j] + red[1][tid][j] + bb;
            y_smA[j * NH + tid] = (v > 0.f) ? v : expm1f(v);
        }
    }
    __syncthreads();

    // ========== P3: heads(A) fused with GEMM1(B) ==========
    {
        const int c  = tid & 127;
        const int kq = tid >> 7;
        const float* Wp; int stride, cc;
        head_sel(c, W_country, W_type, W_taste, W_grape, W_aroma, &Wp, &stride, &cc);

        ull acch[8], accg[8];
        #pragma unroll
        for (int j = 0; j < 8; j++) { acch[j] = 0ull; accg[j] = 0ull; }
        const int kbH = kq * 64;
        const int kbG = kq * 128;

        #pragma unroll 2
        for (int it = 0; it < 16; it++) {
            GEMM_STEP(W_common, NH, c, x_smB, NY, kbG + (2 * it + 0) * 4, accg);
            GEMM_STEP(Wp, stride, cc, y_smA, NH, kbH + it * 4, acch);
            GEMM_STEP(W_common, NH, c, x_smB, NY, kbG + (2 * it + 1) * 4, accg);
        }
        #pragma unroll
        for (int j = 0; j < 8; j++) {
            float lo, hi;
            UNPACK2(lo, hi, accg[j]);
            red[kq][c][j] = lo + hi;
        }
        if (c < 120) {
            #pragma unroll
            for (int j = 0; j < 8; j++) {
                float lo, hi;
                UNPACK2(lo, hi, acch[j]);
                redH[kq][c][j] = lo + hi;
            }
        }
    }
    __syncthreads();

    // P3b: tid<128 -> y_B (elu); tid in [128,248) -> heads(A) finalize
    if (tid < NH) {
        float bb = b_common[tid];
        #pragma unroll
        for (int j = 0; j < 8; j++) {
            float v = red[0][tid][j] + red[1][tid][j] + bb;
            y_smB[j * NH + tid] = (v > 0.f) ? v : expm1f(v);
        }
    } else if (tid < 128 + 120) {
        const int c = tid - 128;
        float s[8];
        #pragma unroll
        for (int j = 0; j < 8; j++) s[j] = redH[0][c][j] + redH[1][c][j];
        if (c < NNC) {
            float bb = b_country[c];
            #pragma unroll
            for (int j = 0; j < 8; j++)
                out[(size_t)(b0 + j) * NNC + c] = s[j] + bb;
        } else if (c == NNC) {
            float bb = b_type[0];
            #pragma unroll
            for (int j = 0; j < 8; j++)
                out[(size_t)NB * NNC + (b0 + j)] = sigmoidf_(s[j] + bb);
        } else if (c < 56) {
            const int cc = c - 51;
            float bb = b_taste[cc];
            #pragma unroll
            for (int j = 0; j < 8; j++)
                out[(size_t)NB * 51 + (size_t)(b0 + j) * NNT + cc] = sigmoidf_(s[j] + bb);
        } else if (c < 88) {
            const int e = c - 56;
            float bb = b_grape[e];
            #pragma unroll
            for (int j = 0; j < 8; j++) yg_sm[j * NE + e] = s[j] + bb;
        } else {
            const int e = c - 88;
            float bb = b_aroma[e];
            #pragma unroll
            for (int j = 0; j < 8; j++) ya_sm[j * NE + e] = s[j] + bb;
        }
    }
    __syncthreads();

    // ========== P4: heads(B) then ragged(A) (independent; back-to-back) ==========
    {
        const int c  = tid & 127;
        const int kq = tid >> 7;
        const float* Wp; int stride, cc;
        head_sel(c, W_country, W_type, W_taste, W_grape, W_aroma, &Wp, &stride, &cc);

        ull acch[8];
        #pragma unroll
        for (int j = 0; j < 8; j++) acch[j] = 0ull;
        const int kbH = kq * 64;
        #pragma unroll 4
        for (int it = 0; it < 16; it++)
            GEMM_STEP(Wp, stride, cc, y_smB, NH, kbH + it * 4, acch);
        if (c < 120) {
            #pragma unroll
            for (int j = 0; j < 8; j++) {
                float lo, hi;
                UNPACK2(lo, hi, acch[j]);
                redH[kq][c][j] = lo + hi;
            }
        }
    }
    ragged_group(tid, b0, grapes, grapes_scales, aromas, aromas_scales,
                 grapes_emb, aroma_emb, yg_sm, ya_sm, out);
    __syncthreads();

    // P4b: heads(B) finalize
    if (tid < 120) {
        const int c = tid;
        float s[8];
        #pragma unroll
        for (int j = 0; j < 8; j++) s[j] = redH[0][c][j] + redH[1][c][j];
        if (c < NNC) {
            float bb = b_country[c];
            #pragma unroll
            for (int j = 0; j < 8; j++)
                out[(size_t)(b0 + 8 + j) * NNC + c] = s[j] + bb;
        } else if (c == NNC) {
            float bb = b_type[0];
            #pragma unroll
            for (int j = 0; j < 8; j++)
                out[(size_t)NB * NNC + (b0 + 8 + j)] = sigmoidf_(s[j] + bb);
        } else if (c < 56) {
            const int cc = c - 51;
            float bb = b_taste[cc];
            #pragma unroll
            for (int j = 0; j < 8; j++)
                out[(size_t)NB * 51 + (size_t)(b0 + 8 + j) * NNT + cc] = sigmoidf_(s[j] + bb);
        } else if (c < 88) {
            const int e = c - 56;
            float bb = b_grape[e];
            #pragma unroll
            for (int j = 0; j < 8; j++) yg_sm[(8 + j) * NE + e] = s[j] + bb;
        } else {
            const int e = c - 88;
            float bb = b_aroma[e];
            #pragma unroll
            for (int j = 0; j < 8; j++) ya_sm[(8 + j) * NE + e] = s[j] + bb;
        }
    }
    __syncthreads();

    // P5: ragged(B)
    ragged_group(tid, b0 + 8, grapes, grapes_scales, aromas, aromas_scales,
                 grapes_emb, aroma_emb, yg_sm + 8 * NE, ya_sm + 8 * NE, out);
}

extern "C" void kernel_launch(void* const* d_in, const int* in_sizes, int n_in,
                              void* d_out, int out_size) {
    const float* x_enc          = (const float*)d_in[0];
    const int*   grapes         = (const int*)  d_in[1];
    const float* grapes_scales  = (const float*)d_in[2];
    const int*   aromas         = (const int*)  d_in[3];
    const float* aromas_scales  = (const float*)d_in[4];
    const float* W_common       = (const float*)d_in[5];
    const float* b_common       = (const float*)d_in[6];
    const float* W_country      = (const float*)d_in[7];
    const float* b_country      = (const float*)d_in[8];
    const float* W_type         = (const float*)d_in[9];
    const float* b_type         = (const float*)d_in[10];
    const float* W_taste        = (const float*)d_in[11];
    const float* b_taste        = (const float*)d_in[12];
    const float* W_aroma        = (const float*)d_in[13];
    const float* b_aroma        = (const float*)d_in[14];
    const float* W_grape        = (const float*)d_in[15];
    const float* b_grape        = (const float*)d_in[16];
    const float* grapes_emb     = (const float*)d_in[17];
    const float* aroma_emb      = (const float*)d_in[18];
    float* out = (float*)d_out;

    wine_fused<<<NB / 16, 256>>>(reinterpret_cast<const float4*>(x_enc),
                                 grapes, grapes_scales, aromas, aromas_scales,
                                 W_common, b_common, W_country, b_country,
                                 W_type, b_type, W_taste, b_taste,
                                 W_aroma, b_aroma, W_grape, b_grape,
                                 grapes_emb, aroma_emb, out);
}